// round 1
// baseline (speedup 1.0000x reference)
#include <cuda_runtime.h>
#include <cuda_bf16.h>

// Problem constants
#define N_NODES 50000
#define N_EDGES 800000
// D_FEAT = CH = 128, HID = 64 for both layers

// ---------------- scratch (device globals; no allocation allowed) ------------
__device__ int   g_cnt[N_NODES];
__device__ int   g_rowstart[N_NODES + 1];
__device__ int   g_wp[N_NODES];
__device__ int   g_srcs[N_EDGES];        // senders grouped by receiver (CSR payload)
__device__ float g_A[N_NODES * 64];      // x @ W1_top + b1
__device__ float g_B[N_NODES * 64];      // x @ W1_bot
__device__ float g_h1[N_NODES * 128];    // layer-1 output
__device__ float g_h2[N_NODES * 128];    // layer-2 output

// ---------------- CSR construction ------------------------------------------
__global__ void zero_cnt_kernel() {
    int i = blockIdx.x * blockDim.x + threadIdx.x;
    if (i < N_NODES) g_cnt[i] = 0;
}

__global__ void hist_kernel(const int* __restrict__ receivers) {
    int e = blockIdx.x * blockDim.x + threadIdx.x;
    if (e < N_EDGES) atomicAdd(&g_cnt[receivers[e]], 1);
}

// single-block exclusive scan over g_cnt -> g_rowstart / g_wp
__global__ void scan_kernel() {
    __shared__ int wsum[32];
    __shared__ int carry;
    int t = threadIdx.x;
    int lane = t & 31, wid = t >> 5;
    if (t == 0) carry = 0;
    __syncthreads();
    for (int base = 0; base < N_NODES; base += 1024) {
        int i = base + t;
        int v = (i < N_NODES) ? g_cnt[i] : 0;
        int x = v;
#pragma unroll
        for (int o = 1; o < 32; o <<= 1) {
            int y = __shfl_up_sync(0xffffffffu, x, o);
            if (lane >= o) x += y;
        }
        if (lane == 31) wsum[wid] = x;
        __syncthreads();
        if (wid == 0) {
            int s = wsum[lane];
#pragma unroll
            for (int o = 1; o < 32; o <<= 1) {
                int y = __shfl_up_sync(0xffffffffu, s, o);
                if (lane >= o) s += y;
            }
            wsum[lane] = s;
        }
        __syncthreads();
        int excl = carry + (x - v) + (wid > 0 ? wsum[wid - 1] : 0);
        if (i < N_NODES) { g_rowstart[i] = excl; g_wp[i] = excl; }
        __syncthreads();
        if (t == 0) carry += wsum[31];
        __syncthreads();
    }
    if (t == 0) g_rowstart[N_NODES] = carry;
}

__global__ void fill_kernel(const int* __restrict__ senders,
                            const int* __restrict__ receivers) {
    int e = blockIdx.x * blockDim.x + threadIdx.x;
    if (e < N_EDGES) {
        int r = receivers[e];
        int pos = atomicAdd(&g_wp[r], 1);
        g_srcs[pos] = senders[e];
    }
}

// ---------------- per-node A/B precompute: A = in @ W1[0:128] + b1, B = in @ W1[128:256]
// in: [N,128] row-major, W1: [256,64] row-major.
__global__ __launch_bounds__(128) void node_ab_kernel(
    const float* __restrict__ in, const float* __restrict__ W1,
    const float* __restrict__ b1, float* __restrict__ A, float* __restrict__ B) {
    __shared__ float xs[16][128];
    int t = threadIdx.x;
    int n0 = blockIdx.x * 16;
    {
        const float4* src = (const float4*)(in + (size_t)n0 * 128);
        float4* dst = (float4*)&xs[0][0];
#pragma unroll
        for (int i = 0; i < 4; i++) dst[t + i * 128] = src[t + i * 128];
    }
    __syncthreads();
    int half = t >> 6, j = t & 63;
    const float* Wb = W1 + half * (128 * 64) + j;
    float acc[16];
    float binit = half ? 0.f : b1[j];
#pragma unroll
    for (int nn = 0; nn < 16; nn++) acc[nn] = binit;
#pragma unroll 4
    for (int k = 0; k < 128; k++) {
        float w = __ldg(Wb + k * 64);
#pragma unroll
        for (int nn = 0; nn < 16; nn++) acc[nn] = fmaf(xs[nn][k], w, acc[nn]);
    }
    float* out = half ? B : A;
#pragma unroll
    for (int nn = 0; nn < 16; nn++) out[(size_t)(n0 + nn) * 64 + j] = acc[nn];
}

// ---------------- hot kernel: warp-per-node edge aggregation -----------------
// For each node n: mean over incoming edges of relu( relu(A[n]+B[s]) @ W2 + b2 )
// Lane owns channels 4*lane .. 4*lane+3 (float4). h[64] distributed 2/lane,
// broadcast via shfl. W2 [64,128] in shared, read as float4 (conflict-free).
__global__ __launch_bounds__(256) void aggregate_kernel(
    const float* __restrict__ A, const float* __restrict__ B,
    const float* __restrict__ W2, const float* __restrict__ b2,
    float* __restrict__ out) {
    __shared__ float W2s[64 * 128];
    int t = threadIdx.x;
    {
        const float4* src = (const float4*)W2;
        float4* dst = (float4*)W2s;
#pragma unroll
        for (int i = 0; i < 8; i++) dst[t + i * 256] = src[t + i * 256];
    }
    __syncthreads();
    int warp = t >> 5, lane = t & 31;
    int n = blockIdx.x * 8 + warp;
    if (n >= N_NODES) return;
    int e0 = g_rowstart[n], e1 = g_rowstart[n + 1];
    float a0 = A[(size_t)n * 64 + lane];
    float a1 = A[(size_t)n * 64 + 32 + lane];
    float4 bb = ((const float4*)b2)[lane];
    const float4* W2v = (const float4*)W2s;
    float4 acc = make_float4(0.f, 0.f, 0.f, 0.f);
    for (int e = e0; e < e1; ++e) {
        int s = g_srcs[e];
        float h0 = fmaxf(a0 + B[(size_t)s * 64 + lane], 0.f);
        float h1 = fmaxf(a1 + B[(size_t)s * 64 + 32 + lane], 0.f);
        float4 m = make_float4(0.f, 0.f, 0.f, 0.f);
#pragma unroll
        for (int k = 0; k < 32; k++) {
            float hk0 = __shfl_sync(0xffffffffu, h0, k);
            float4 w = W2v[k * 32 + lane];
            m.x = fmaf(w.x, hk0, m.x);
            m.y = fmaf(w.y, hk0, m.y);
            m.z = fmaf(w.z, hk0, m.z);
            m.w = fmaf(w.w, hk0, m.w);
            float hk1 = __shfl_sync(0xffffffffu, h1, k);
            float4 w2 = W2v[(k + 32) * 32 + lane];
            m.x = fmaf(w2.x, hk1, m.x);
            m.y = fmaf(w2.y, hk1, m.y);
            m.z = fmaf(w2.z, hk1, m.z);
            m.w = fmaf(w2.w, hk1, m.w);
        }
        acc.x += fmaxf(m.x + bb.x, 0.f);
        acc.y += fmaxf(m.y + bb.y, 0.f);
        acc.z += fmaxf(m.z + bb.z, 0.f);
        acc.w += fmaxf(m.w + bb.w, 0.f);
    }
    float inv = (e1 > e0) ? 1.f / (float)(e1 - e0) : 0.f;
    acc.x *= inv; acc.y *= inv; acc.z *= inv; acc.w *= inv;
    ((float4*)out)[(size_t)n * 32 + lane] = acc;
}

// ---------------- dense tail: out = relu(h @ Wd1 + bd1) @ Wd2 + bd2 ----------
__global__ __launch_bounds__(256) void tail_kernel(
    const float* __restrict__ h, const float* __restrict__ Wd1,
    const float* __restrict__ bd1, const float* __restrict__ Wd2,
    const float* __restrict__ bd2, float* __restrict__ out) {
    __shared__ float Ws[128 * 64];
    int t = threadIdx.x;
    {
        const float4* src = (const float4*)Wd1;
        float4* dst = (float4*)Ws;
#pragma unroll
        for (int i = 0; i < 8; i++) dst[t + i * 256] = src[t + i * 256];
    }
    __syncthreads();
    int warp = t >> 5, lane = t & 31;
    int n = blockIdx.x * 8 + warp;
    if (n >= N_NODES) return;
    float x0 = h[(size_t)n * 128 + lane];
    float x1 = h[(size_t)n * 128 + 32 + lane];
    float x2 = h[(size_t)n * 128 + 64 + lane];
    float x3 = h[(size_t)n * 128 + 96 + lane];
    float g0 = bd1[lane], g1 = bd1[lane + 32];
#pragma unroll
    for (int kk = 0; kk < 32; kk++) {
        float xk;
        xk = __shfl_sync(0xffffffffu, x0, kk);
        g0 = fmaf(xk, Ws[kk * 64 + lane], g0);
        g1 = fmaf(xk, Ws[kk * 64 + lane + 32], g1);
        xk = __shfl_sync(0xffffffffu, x1, kk);
        g0 = fmaf(xk, Ws[(kk + 32) * 64 + lane], g0);
        g1 = fmaf(xk, Ws[(kk + 32) * 64 + lane + 32], g1);
        xk = __shfl_sync(0xffffffffu, x2, kk);
        g0 = fmaf(xk, Ws[(kk + 64) * 64 + lane], g0);
        g1 = fmaf(xk, Ws[(kk + 64) * 64 + lane + 32], g1);
        xk = __shfl_sync(0xffffffffu, x3, kk);
        g0 = fmaf(xk, Ws[(kk + 96) * 64 + lane], g0);
        g1 = fmaf(xk, Ws[(kk + 96) * 64 + lane + 32], g1);
    }
    g0 = fmaxf(g0, 0.f);
    g1 = fmaxf(g1, 0.f);
    float p = g0 * Wd2[lane] + g1 * Wd2[lane + 32];
#pragma unroll
    for (int o = 16; o > 0; o >>= 1) p += __shfl_xor_sync(0xffffffffu, p, o);
    if (lane == 0) out[n] = p + bd2[0];
}

// ---------------- launch ------------------------------------------------------
extern "C" void kernel_launch(void* const* d_in, const int* in_sizes, int n_in,
                              void* d_out, int out_size) {
    const float* x         = (const float*)d_in[0];
    const int*   senders   = (const int*)d_in[1];
    const int*   receivers = (const int*)d_in[2];
    const float* W1a = (const float*)d_in[3];
    const float* b1a = (const float*)d_in[4];
    const float* W2a = (const float*)d_in[5];
    const float* b2a = (const float*)d_in[6];
    const float* W1b = (const float*)d_in[7];
    const float* b1b = (const float*)d_in[8];
    const float* W2b = (const float*)d_in[9];
    const float* b2b = (const float*)d_in[10];
    const float* Wd1 = (const float*)d_in[11];
    const float* bd1 = (const float*)d_in[12];
    const float* Wd2 = (const float*)d_in[13];
    const float* bd2 = (const float*)d_in[14];
    float* out = (float*)d_out;

    // device-global symbol pointers are used directly inside kernels; for
    // kernels taking A/B/h pointers, fetch raw addresses via small launches.
    // We pass them through static device symbols resolved at compile time by
    // referencing the arrays in wrapper lambdas is not possible, so use
    // cudaGetSymbolAddress-free approach: kernels that need them take them as
    // arguments obtained below (symbol address query is not a stream op and
    // is graph-capture safe, but we avoid it entirely by direct reference).

    // CSR build
    zero_cnt_kernel<<<(N_NODES + 255) / 256, 256>>>();
    hist_kernel<<<(N_EDGES + 255) / 256, 256>>>(receivers);
    scan_kernel<<<1, 1024>>>();
    fill_kernel<<<(N_EDGES + 255) / 256, 256>>>(senders, receivers);

    // Resolve scratch addresses (host-side; capture-safe, no alloc)
    static float* pA = nullptr;
    static float* pB = nullptr;
    static float* pH1 = nullptr;
    static float* pH2 = nullptr;
    if (!pA) {
        cudaGetSymbolAddress((void**)&pA, g_A);
        cudaGetSymbolAddress((void**)&pB, g_B);
        cudaGetSymbolAddress((void**)&pH1, g_h1);
        cudaGetSymbolAddress((void**)&pH2, g_h2);
    }

    // Layer 1
    node_ab_kernel<<<N_NODES / 16, 128>>>(x, W1a, b1a, pA, pB);
    aggregate_kernel<<<(N_NODES + 7) / 8, 256>>>(pA, pB, W2a, b2a, pH1);
    // Layer 2
    node_ab_kernel<<<N_NODES / 16, 128>>>(pH1, W1b, b1b, pA, pB);
    aggregate_kernel<<<(N_NODES + 7) / 8, 256>>>(pA, pB, W2b, b2b, pH2);
    // Dense tail
    tail_kernel<<<(N_NODES + 7) / 8, 256>>>(pH2, Wd1, bd1, Wd2, bd2, out);
}

// round 2
// speedup vs baseline: 1.2888x; 1.2888x over previous
#include <cuda_runtime.h>
#include <cuda_bf16.h>

// Problem constants
#define N_NODES 50000
#define N_EDGES 800000
// D_FEAT = CH = 128, HID = 64 for both layers

// ---------------- scratch (device globals; no allocation allowed) ------------
__device__ int   g_cnt[N_NODES];
__device__ int   g_rowstart[N_NODES + 1];
__device__ int   g_wp[N_NODES];
__device__ int   g_srcs[N_EDGES];        // senders grouped by receiver (CSR payload)
__device__ float g_A[N_NODES * 64];      // x @ W1_top + b1
__device__ float g_B[N_NODES * 64];      // x @ W1_bot
__device__ float g_h1[N_NODES * 128];    // layer-1 output
__device__ float g_h2[N_NODES * 128];    // layer-2 output

// ---------------- packed f32x2 helpers ---------------------------------------
__device__ __forceinline__ unsigned long long pk2(float lo, float hi) {
    unsigned long long r;
    asm("mov.b64 %0, {%1, %2};" : "=l"(r)
        : "r"(__float_as_uint(lo)), "r"(__float_as_uint(hi)));
    return r;
}
__device__ __forceinline__ void upk2(unsigned long long v, float& lo, float& hi) {
    unsigned int a, b;
    asm("mov.b64 {%0, %1}, %2;" : "=r"(a), "=r"(b) : "l"(v));
    lo = __uint_as_float(a);
    hi = __uint_as_float(b);
}
#define FMA2(m, a, b) \
    asm("fma.rn.f32x2 %0, %1, %2, %0;" : "+l"(m) : "l"(a), "l"(b))

// ---------------- CSR construction ------------------------------------------
__global__ void zero_cnt_kernel() {
    int i = blockIdx.x * blockDim.x + threadIdx.x;
    if (i < N_NODES) g_cnt[i] = 0;
}

__global__ void hist_kernel(const int* __restrict__ receivers) {
    int e = blockIdx.x * blockDim.x + threadIdx.x;
    if (e < N_EDGES) atomicAdd(&g_cnt[receivers[e]], 1);
}

// single-block exclusive scan over g_cnt -> g_rowstart / g_wp
__global__ void scan_kernel() {
    __shared__ int wsum[32];
    __shared__ int carry;
    int t = threadIdx.x;
    int lane = t & 31, wid = t >> 5;
    if (t == 0) carry = 0;
    __syncthreads();
    for (int base = 0; base < N_NODES; base += 1024) {
        int i = base + t;
        int v = (i < N_NODES) ? g_cnt[i] : 0;
        int x = v;
#pragma unroll
        for (int o = 1; o < 32; o <<= 1) {
            int y = __shfl_up_sync(0xffffffffu, x, o);
            if (lane >= o) x += y;
        }
        if (lane == 31) wsum[wid] = x;
        __syncthreads();
        if (wid == 0) {
            int s = wsum[lane];
#pragma unroll
            for (int o = 1; o < 32; o <<= 1) {
                int y = __shfl_up_sync(0xffffffffu, s, o);
                if (lane >= o) s += y;
            }
            wsum[lane] = s;
        }
        __syncthreads();
        int excl = carry + (x - v) + (wid > 0 ? wsum[wid - 1] : 0);
        if (i < N_NODES) { g_rowstart[i] = excl; g_wp[i] = excl; }
        __syncthreads();
        if (t == 0) carry += wsum[31];
        __syncthreads();
    }
    if (t == 0) g_rowstart[N_NODES] = carry;
}

__global__ void fill_kernel(const int* __restrict__ senders,
                            const int* __restrict__ receivers) {
    int e = blockIdx.x * blockDim.x + threadIdx.x;
    if (e < N_EDGES) {
        int r = receivers[e];
        int pos = atomicAdd(&g_wp[r], 1);
        g_srcs[pos] = senders[e];
    }
}

// ---------------- per-node A/B precompute ------------------------------------
// A = in @ W1[0:128] + b1, B = in @ W1[128:256]. in: [N,128], W1: [256,64].
__global__ __launch_bounds__(128) void node_ab_kernel(
    const float* __restrict__ in, const float* __restrict__ W1,
    const float* __restrict__ b1, float* __restrict__ A, float* __restrict__ B) {
    __shared__ float xs[16][128];
    int t = threadIdx.x;
    int n0 = blockIdx.x * 16;
    {
        const float4* src = (const float4*)(in + (size_t)n0 * 128);
        float4* dst = (float4*)&xs[0][0];
#pragma unroll
        for (int i = 0; i < 4; i++) dst[t + i * 128] = src[t + i * 128];
    }
    __syncthreads();
    int half = t >> 6, j = t & 63;
    const float* Wb = W1 + half * (128 * 64) + j;
    float acc[16];
    float binit = half ? 0.f : b1[j];
#pragma unroll
    for (int nn = 0; nn < 16; nn++) acc[nn] = binit;
#pragma unroll 4
    for (int k = 0; k < 128; k++) {
        float w = __ldg(Wb + k * 64);
#pragma unroll
        for (int nn = 0; nn < 16; nn++) acc[nn] = fmaf(xs[nn][k], w, acc[nn]);
    }
    float* out = half ? B : A;
#pragma unroll
    for (int nn = 0; nn < 16; nn++) out[(size_t)(n0 + nn) * 64 + j] = acc[nn];
}

// ---------------- hot kernel: warp-per-node, EB-edge batched, f32x2 ----------
// node n: mean over incoming edges of relu( relu(A[n]+B[s]) @ W2 + b2 )
// Lane owns 4 channels. h[64] per edge lives 2 floats/lane, broadcast via shfl.
// One W2 LDS.128 per k serves EB edges (smem traffic /EB). FMA in packed f32x2.
template<int EB>
__device__ __forceinline__ void process_chunk(
    int e, int e1, const float* __restrict__ B, float a0, float a1, int lane,
    const float4* __restrict__ W2v, float4 bb, float4& acc) {
    float h0[EB], h1[EB];
#pragma unroll
    for (int i = 0; i < EB; i++) {
        int ei = e + i;
        int s = g_srcs[ei < e1 ? ei : e];   // e < e1 guaranteed by caller
        h0[i] = fmaxf(a0 + B[(size_t)s * 64 + lane], 0.f);
        h1[i] = fmaxf(a1 + B[(size_t)s * 64 + 32 + lane], 0.f);
    }
    unsigned long long m01[EB], m23[EB];
#pragma unroll
    for (int i = 0; i < EB; i++) { m01[i] = 0ull; m23[i] = 0ull; }
#pragma unroll 8
    for (int k = 0; k < 32; k++) {
        float4 w = W2v[k * 32 + lane];
        unsigned long long w01 = pk2(w.x, w.y);
        unsigned long long w23 = pk2(w.z, w.w);
#pragma unroll
        for (int i = 0; i < EB; i++) {
            float hk = __shfl_sync(0xffffffffu, h0[i], k);
            unsigned long long hh = pk2(hk, hk);
            FMA2(m01[i], w01, hh);
            FMA2(m23[i], w23, hh);
        }
        float4 v = W2v[(k + 32) * 32 + lane];
        unsigned long long v01 = pk2(v.x, v.y);
        unsigned long long v23 = pk2(v.z, v.w);
#pragma unroll
        for (int i = 0; i < EB; i++) {
            float hk = __shfl_sync(0xffffffffu, h1[i], k);
            unsigned long long hh = pk2(hk, hk);
            FMA2(m01[i], v01, hh);
            FMA2(m23[i], v23, hh);
        }
    }
#pragma unroll
    for (int i = 0; i < EB; i++) {
        if (e + i < e1) {
            float x0, x1, x2, x3;
            upk2(m01[i], x0, x1);
            upk2(m23[i], x2, x3);
            acc.x += fmaxf(x0 + bb.x, 0.f);
            acc.y += fmaxf(x1 + bb.y, 0.f);
            acc.z += fmaxf(x2 + bb.z, 0.f);
            acc.w += fmaxf(x3 + bb.w, 0.f);
        }
    }
}

__global__ __launch_bounds__(256) void aggregate_kernel(
    const float* __restrict__ A, const float* __restrict__ B,
    const float* __restrict__ W2, const float* __restrict__ b2,
    float* __restrict__ out) {
    __shared__ float W2s[64 * 128];
    int t = threadIdx.x;
    {
        const float4* src = (const float4*)W2;
        float4* dst = (float4*)W2s;
#pragma unroll
        for (int i = 0; i < 8; i++) dst[t + i * 256] = src[t + i * 256];
    }
    __syncthreads();
    int warp = t >> 5, lane = t & 31;
    int n = blockIdx.x * 8 + warp;
    if (n >= N_NODES) return;
    int e0 = g_rowstart[n], e1 = g_rowstart[n + 1];
    float a0 = A[(size_t)n * 64 + lane];
    float a1 = A[(size_t)n * 64 + 32 + lane];
    float4 bb = ((const float4*)b2)[lane];
    const float4* W2v = (const float4*)W2s;
    float4 acc = make_float4(0.f, 0.f, 0.f, 0.f);

    int e = e0;
    for (; e + 8 <= e1; e += 8)
        process_chunk<8>(e, e1, B, a0, a1, lane, W2v, bb, acc);
    for (; e < e1; e += 4)
        process_chunk<4>(e, e1, B, a0, a1, lane, W2v, bb, acc);

    float inv = (e1 > e0) ? 1.f / (float)(e1 - e0) : 0.f;
    acc.x *= inv; acc.y *= inv; acc.z *= inv; acc.w *= inv;
    ((float4*)out)[(size_t)n * 32 + lane] = acc;
}

// ---------------- dense tail: out = relu(h @ Wd1 + bd1) @ Wd2 + bd2 ----------
__global__ __launch_bounds__(256) void tail_kernel(
    const float* __restrict__ h, const float* __restrict__ Wd1,
    const float* __restrict__ bd1, const float* __restrict__ Wd2,
    const float* __restrict__ bd2, float* __restrict__ out) {
    __shared__ float Ws[128 * 64];
    int t = threadIdx.x;
    {
        const float4* src = (const float4*)Wd1;
        float4* dst = (float4*)Ws;
#pragma unroll
        for (int i = 0; i < 8; i++) dst[t + i * 256] = src[t + i * 256];
    }
    __syncthreads();
    int warp = t >> 5, lane = t & 31;
    int n = blockIdx.x * 8 + warp;
    if (n >= N_NODES) return;
    float x0 = h[(size_t)n * 128 + lane];
    float x1 = h[(size_t)n * 128 + 32 + lane];
    float x2 = h[(size_t)n * 128 + 64 + lane];
    float x3 = h[(size_t)n * 128 + 96 + lane];
    float g0 = bd1[lane], g1 = bd1[lane + 32];
#pragma unroll
    for (int kk = 0; kk < 32; kk++) {
        float xk;
        xk = __shfl_sync(0xffffffffu, x0, kk);
        g0 = fmaf(xk, Ws[kk * 64 + lane], g0);
        g1 = fmaf(xk, Ws[kk * 64 + lane + 32], g1);
        xk = __shfl_sync(0xffffffffu, x1, kk);
        g0 = fmaf(xk, Ws[(kk + 32) * 64 + lane], g0);
        g1 = fmaf(xk, Ws[(kk + 32) * 64 + lane + 32], g1);
        xk = __shfl_sync(0xffffffffu, x2, kk);
        g0 = fmaf(xk, Ws[(kk + 64) * 64 + lane], g0);
        g1 = fmaf(xk, Ws[(kk + 64) * 64 + lane + 32], g1);
        xk = __shfl_sync(0xffffffffu, x3, kk);
        g0 = fmaf(xk, Ws[(kk + 96) * 64 + lane], g0);
        g1 = fmaf(xk, Ws[(kk + 96) * 64 + lane + 32], g1);
    }
    g0 = fmaxf(g0, 0.f);
    g1 = fmaxf(g1, 0.f);
    float p = g0 * Wd2[lane] + g1 * Wd2[lane + 32];
#pragma unroll
    for (int o = 16; o > 0; o >>= 1) p += __shfl_xor_sync(0xffffffffu, p, o);
    if (lane == 0) out[n] = p + bd2[0];
}

// ---------------- launch ------------------------------------------------------
extern "C" void kernel_launch(void* const* d_in, const int* in_sizes, int n_in,
                              void* d_out, int out_size) {
    const float* x         = (const float*)d_in[0];
    const int*   senders   = (const int*)d_in[1];
    const int*   receivers = (const int*)d_in[2];
    const float* W1a = (const float*)d_in[3];
    const float* b1a = (const float*)d_in[4];
    const float* W2a = (const float*)d_in[5];
    const float* b2a = (const float*)d_in[6];
    const float* W1b = (const float*)d_in[7];
    const float* b1b = (const float*)d_in[8];
    const float* W2b = (const float*)d_in[9];
    const float* b2b = (const float*)d_in[10];
    const float* Wd1 = (const float*)d_in[11];
    const float* bd1 = (const float*)d_in[12];
    const float* Wd2 = (const float*)d_in[13];
    const float* bd2 = (const float*)d_in[14];
    float* out = (float*)d_out;

    // CSR build
    zero_cnt_kernel<<<(N_NODES + 255) / 256, 256>>>();
    hist_kernel<<<(N_EDGES + 255) / 256, 256>>>(receivers);
    scan_kernel<<<1, 1024>>>();
    fill_kernel<<<(N_EDGES + 255) / 256, 256>>>(senders, receivers);

    // Resolve scratch addresses (host-side; capture-safe, no alloc)
    static float* pA = nullptr;
    static float* pB = nullptr;
    static float* pH1 = nullptr;
    static float* pH2 = nullptr;
    if (!pA) {
        cudaGetSymbolAddress((void**)&pA, g_A);
        cudaGetSymbolAddress((void**)&pB, g_B);
        cudaGetSymbolAddress((void**)&pH1, g_h1);
        cudaGetSymbolAddress((void**)&pH2, g_h2);
    }

    // Layer 1
    node_ab_kernel<<<N_NODES / 16, 128>>>(x, W1a, b1a, pA, pB);
    aggregate_kernel<<<(N_NODES + 7) / 8, 256>>>(pA, pB, W2a, b2a, pH1);
    // Layer 2
    node_ab_kernel<<<N_NODES / 16, 128>>>(pH1, W1b, b1b, pA, pB);
    aggregate_kernel<<<(N_NODES + 7) / 8, 256>>>(pA, pB, W2b, b2b, pH2);
    // Dense tail
    tail_kernel<<<(N_NODES + 7) / 8, 256>>>(pH2, Wd1, bd1, Wd2, bd2, out);
}

// round 3
// speedup vs baseline: 1.9765x; 1.5336x over previous
#include <cuda_runtime.h>
#include <cuda_bf16.h>

// Problem constants
#define N_NODES 50000
#define N_EDGES 800000
// D_FEAT = CH = 128, HID = 64 for both layers

// ---------------- scratch (device globals; no allocation allowed) ------------
__device__ int   g_cnt[N_NODES];
__device__ int   g_rowstart[N_NODES + 1];
__device__ int   g_wp[N_NODES];
__device__ int   g_srcs[N_EDGES];        // senders grouped by receiver (CSR payload)
__device__ float g_A[N_NODES * 64];      // x @ W1_top + b1
__device__ float g_B[N_NODES * 64];      // x @ W1_bot
__device__ float g_h1[N_NODES * 128];    // layer-1 output
__device__ float g_h2[N_NODES * 128];    // layer-2 output

// ---------------- packed f32x2 helpers ---------------------------------------
__device__ __forceinline__ unsigned long long pk2(float lo, float hi) {
    unsigned long long r;
    asm("mov.b64 %0, {%1, %2};" : "=l"(r)
        : "r"(__float_as_uint(lo)), "r"(__float_as_uint(hi)));
    return r;
}
__device__ __forceinline__ void upk2(unsigned long long v, float& lo, float& hi) {
    unsigned int a, b;
    asm("mov.b64 {%0, %1}, %2;" : "=r"(a), "=r"(b) : "l"(v));
    lo = __uint_as_float(a);
    hi = __uint_as_float(b);
}
#define FMA2(m, a, b) \
    asm("fma.rn.f32x2 %0, %1, %2, %0;" : "+l"(m) : "l"(a), "l"(b))

// ---------------- CSR construction ------------------------------------------
__global__ void zero_cnt_kernel() {
    int i = blockIdx.x * blockDim.x + threadIdx.x;
    if (i < N_NODES) g_cnt[i] = 0;
}

__global__ void hist_kernel(const int* __restrict__ receivers) {
    int e = blockIdx.x * blockDim.x + threadIdx.x;
    if (e < N_EDGES) atomicAdd(&g_cnt[receivers[e]], 1);
}

// single-block exclusive scan over g_cnt -> g_rowstart / g_wp
__global__ void scan_kernel() {
    __shared__ int wsum[32];
    __shared__ int carry;
    int t = threadIdx.x;
    int lane = t & 31, wid = t >> 5;
    if (t == 0) carry = 0;
    __syncthreads();
    for (int base = 0; base < N_NODES; base += 1024) {
        int i = base + t;
        int v = (i < N_NODES) ? g_cnt[i] : 0;
        int x = v;
#pragma unroll
        for (int o = 1; o < 32; o <<= 1) {
            int y = __shfl_up_sync(0xffffffffu, x, o);
            if (lane >= o) x += y;
        }
        if (lane == 31) wsum[wid] = x;
        __syncthreads();
        if (wid == 0) {
            int s = wsum[lane];
#pragma unroll
            for (int o = 1; o < 32; o <<= 1) {
                int y = __shfl_up_sync(0xffffffffu, s, o);
                if (lane >= o) s += y;
            }
            wsum[lane] = s;
        }
        __syncthreads();
        int excl = carry + (x - v) + (wid > 0 ? wsum[wid - 1] : 0);
        if (i < N_NODES) { g_rowstart[i] = excl; g_wp[i] = excl; }
        __syncthreads();
        if (t == 0) carry += wsum[31];
        __syncthreads();
    }
    if (t == 0) g_rowstart[N_NODES] = carry;
}

__global__ void fill_kernel(const int* __restrict__ senders,
                            const int* __restrict__ receivers) {
    int e = blockIdx.x * blockDim.x + threadIdx.x;
    if (e < N_EDGES) {
        int r = receivers[e];
        int pos = atomicAdd(&g_wp[r], 1);
        g_srcs[pos] = senders[e];
    }
}

// ---------------- per-node A/B precompute ------------------------------------
// A = in @ W1[0:128] + b1, B = in @ W1[128:256]. in: [N,128], W1: [256,64].
__global__ __launch_bounds__(128) void node_ab_kernel(
    const float* __restrict__ in, const float* __restrict__ W1,
    const float* __restrict__ b1, float* __restrict__ A, float* __restrict__ B) {
    __shared__ float xs[16][128];
    int t = threadIdx.x;
    int n0 = blockIdx.x * 16;
    {
        const float4* src = (const float4*)(in + (size_t)n0 * 128);
        float4* dst = (float4*)&xs[0][0];
#pragma unroll
        for (int i = 0; i < 4; i++) dst[t + i * 128] = src[t + i * 128];
    }
    __syncthreads();
    int half = t >> 6, j = t & 63;
    const float* Wb = W1 + half * (128 * 64) + j;
    float acc[16];
    float binit = half ? 0.f : b1[j];
#pragma unroll
    for (int nn = 0; nn < 16; nn++) acc[nn] = binit;
#pragma unroll 4
    for (int k = 0; k < 128; k++) {
        float w = __ldg(Wb + k * 64);
#pragma unroll
        for (int nn = 0; nn < 16; nn++) acc[nn] = fmaf(xs[nn][k], w, acc[nn]);
    }
    float* out = half ? B : A;
#pragma unroll
    for (int nn = 0; nn < 16; nn++) out[(size_t)(n0 + nn) * 64 + j] = acc[nn];
}

// ---------------- hot kernel: warp-per-node, smem h-splat, no SHFL ----------
// node n: mean over incoming edges of relu( relu(A[n]+B[s]) @ W2 + b2 )
// Lane owns 4 output channels (ulonglong2 = two f32x2 pairs). Per edge, h[64]
// is computed 2 values/lane and stored SPLATTED ({h,h} 64-bit) to smem; the
// inner loop reads {h[2k],h[2k],h[2k+1],h[2k+1]} with one broadcast LDS.128.
// Weights stream from smem as ulonglong2 (consecutive channel pairs = native
// f32x2 operands). Zero SHFL, zero packing movs in the hot loop.
template<int EB>
__device__ __forceinline__ void process_chunk(
    int e, int e1, const float* __restrict__ B, float a0, float a1, int lane,
    const ulonglong2* __restrict__ W2v, unsigned long long* __restrict__ hw,
    const ulonglong2* __restrict__ hv, float4 bb, float4& acc, bool masked) {
    float r0[EB], r1[EB];
#pragma unroll
    for (int i = 0; i < EB; i++) {
        int ei = e + i;
        int s = g_srcs[(!masked || ei < e1) ? ei : e];
        r0[i] = B[(size_t)s * 64 + lane];
        r1[i] = B[(size_t)s * 64 + 32 + lane];
    }
#pragma unroll
    for (int i = 0; i < EB; i++) {
        float x0 = fmaxf(a0 + r0[i], 0.f);
        float x1 = fmaxf(a1 + r1[i], 0.f);
        hw[i * 64 + lane]      = pk2(x0, x0);
        hw[i * 64 + 32 + lane] = pk2(x1, x1);
    }
    __syncwarp();
    unsigned long long m01[EB], m23[EB];
#pragma unroll
    for (int i = 0; i < EB; i++) { m01[i] = 0ull; m23[i] = 0ull; }
    for (int kk = 0; kk < 32; kk++) {
        ulonglong2 wa = W2v[(2 * kk) * 32 + lane];
        ulonglong2 wb = W2v[(2 * kk + 1) * 32 + lane];
#pragma unroll
        for (int i = 0; i < EB; i++) {
            ulonglong2 hh = hv[i * 32 + kk];
            FMA2(m01[i], wa.x, hh.x);
            FMA2(m23[i], wa.y, hh.x);
            FMA2(m01[i], wb.x, hh.y);
            FMA2(m23[i], wb.y, hh.y);
        }
    }
#pragma unroll
    for (int i = 0; i < EB; i++) {
        if (!masked || e + i < e1) {
            float x0, x1, x2, x3;
            upk2(m01[i], x0, x1);
            upk2(m23[i], x2, x3);
            acc.x += fmaxf(x0 + bb.x, 0.f);
            acc.y += fmaxf(x1 + bb.y, 0.f);
            acc.z += fmaxf(x2 + bb.z, 0.f);
            acc.w += fmaxf(x3 + bb.w, 0.f);
        }
    }
    __syncwarp();
}

__global__ __launch_bounds__(128) void aggregate_kernel(
    const float* __restrict__ A, const float* __restrict__ B,
    const float* __restrict__ W2, const float* __restrict__ b2,
    float* __restrict__ out) {
    extern __shared__ float smemf[];
    float* W2s = smemf;                                        // 32 KB
    unsigned long long* hsm = (unsigned long long*)(smemf + 8192);  // 32 KB
    int t = threadIdx.x;
    {
        const float4* src = (const float4*)W2;
        float4* dst = (float4*)W2s;
#pragma unroll
        for (int i = 0; i < 16; i++) dst[t + i * 128] = src[t + i * 128];
    }
    __syncthreads();
    int warp = t >> 5, lane = t & 31;
    const ulonglong2* W2v = (const ulonglong2*)W2s;
    unsigned long long* hw = hsm + warp * 1024;   // 16 edges * 64 splats
    const ulonglong2* hv = (const ulonglong2*)hw;
    float4 bb = ((const float4*)b2)[lane];

    for (int n = blockIdx.x * 4 + warp; n < N_NODES; n += gridDim.x * 4) {
        int e0 = g_rowstart[n], e1 = g_rowstart[n + 1];
        float a0 = A[(size_t)n * 64 + lane];
        float a1 = A[(size_t)n * 64 + 32 + lane];
        float4 acc = make_float4(0.f, 0.f, 0.f, 0.f);
        int e = e0;
        for (; e + 16 <= e1; e += 16)
            process_chunk<16>(e, e1, B, a0, a1, lane, W2v, hw, hv, bb, acc, false);
        for (; e < e1; e += 4)
            process_chunk<4>(e, e1, B, a0, a1, lane, W2v, hw, hv, bb, acc, true);
        float inv = (e1 > e0) ? 1.f / (float)(e1 - e0) : 0.f;
        acc.x *= inv; acc.y *= inv; acc.z *= inv; acc.w *= inv;
        ((float4*)out)[(size_t)n * 32 + lane] = acc;
    }
}

// ---------------- dense tail: out = relu(h @ Wd1 + bd1) @ Wd2 + bd2 ----------
__global__ __launch_bounds__(256) void tail_kernel(
    const float* __restrict__ h, const float* __restrict__ Wd1,
    const float* __restrict__ bd1, const float* __restrict__ Wd2,
    const float* __restrict__ bd2, float* __restrict__ out) {
    __shared__ float Ws[128 * 64];
    int t = threadIdx.x;
    {
        const float4* src = (const float4*)Wd1;
        float4* dst = (float4*)Ws;
#pragma unroll
        for (int i = 0; i < 8; i++) dst[t + i * 256] = src[t + i * 256];
    }
    __syncthreads();
    int warp = t >> 5, lane = t & 31;
    int n = blockIdx.x * 8 + warp;
    if (n >= N_NODES) return;
    float x0 = h[(size_t)n * 128 + lane];
    float x1 = h[(size_t)n * 128 + 32 + lane];
    float x2 = h[(size_t)n * 128 + 64 + lane];
    float x3 = h[(size_t)n * 128 + 96 + lane];
    float g0 = bd1[lane], g1 = bd1[lane + 32];
#pragma unroll
    for (int kk = 0; kk < 32; kk++) {
        float xk;
        xk = __shfl_sync(0xffffffffu, x0, kk);
        g0 = fmaf(xk, Ws[kk * 64 + lane], g0);
        g1 = fmaf(xk, Ws[kk * 64 + lane + 32], g1);
        xk = __shfl_sync(0xffffffffu, x1, kk);
        g0 = fmaf(xk, Ws[(kk + 32) * 64 + lane], g0);
        g1 = fmaf(xk, Ws[(kk + 32) * 64 + lane + 32], g1);
        xk = __shfl_sync(0xffffffffu, x2, kk);
        g0 = fmaf(xk, Ws[(kk + 64) * 64 + lane], g0);
        g1 = fmaf(xk, Ws[(kk + 64) * 64 + lane + 32], g1);
        xk = __shfl_sync(0xffffffffu, x3, kk);
        g0 = fmaf(xk, Ws[(kk + 96) * 64 + lane], g0);
        g1 = fmaf(xk, Ws[(kk + 96) * 64 + lane + 32], g1);
    }
    g0 = fmaxf(g0, 0.f);
    g1 = fmaxf(g1, 0.f);
    float p = g0 * Wd2[lane] + g1 * Wd2[lane + 32];
#pragma unroll
    for (int o = 16; o > 0; o >>= 1) p += __shfl_xor_sync(0xffffffffu, p, o);
    if (lane == 0) out[n] = p + bd2[0];
}

// ---------------- launch ------------------------------------------------------
extern "C" void kernel_launch(void* const* d_in, const int* in_sizes, int n_in,
                              void* d_out, int out_size) {
    const float* x         = (const float*)d_in[0];
    const int*   senders   = (const int*)d_in[1];
    const int*   receivers = (const int*)d_in[2];
    const float* W1a = (const float*)d_in[3];
    const float* b1a = (const float*)d_in[4];
    const float* W2a = (const float*)d_in[5];
    const float* b2a = (const float*)d_in[6];
    const float* W1b = (const float*)d_in[7];
    const float* b1b = (const float*)d_in[8];
    const float* W2b = (const float*)d_in[9];
    const float* b2b = (const float*)d_in[10];
    const float* Wd1 = (const float*)d_in[11];
    const float* bd1 = (const float*)d_in[12];
    const float* Wd2 = (const float*)d_in[13];
    const float* bd2 = (const float*)d_in[14];
    float* out = (float*)d_out;

    // Resolve scratch addresses + opt-in smem (host-side; capture-safe, no alloc)
    static float* pA = nullptr;
    static float* pB = nullptr;
    static float* pH1 = nullptr;
    static float* pH2 = nullptr;
    if (!pA) {
        cudaGetSymbolAddress((void**)&pA, g_A);
        cudaGetSymbolAddress((void**)&pB, g_B);
        cudaGetSymbolAddress((void**)&pH1, g_h1);
        cudaGetSymbolAddress((void**)&pH2, g_h2);
        cudaFuncSetAttribute(aggregate_kernel,
                             cudaFuncAttributeMaxDynamicSharedMemorySize, 65536);
    }

    // CSR build
    zero_cnt_kernel<<<(N_NODES + 255) / 256, 256>>>();
    hist_kernel<<<(N_EDGES + 255) / 256, 256>>>(receivers);
    scan_kernel<<<1, 1024>>>();
    fill_kernel<<<(N_EDGES + 255) / 256, 256>>>(senders, receivers);

    const int AGG_BLOCKS = 444;   // 148 SM * 3 blocks (64KB smem each), 1 wave
    // Layer 1
    node_ab_kernel<<<N_NODES / 16, 128>>>(x, W1a, b1a, pA, pB);
    aggregate_kernel<<<AGG_BLOCKS, 128, 65536>>>(pA, pB, W2a, b2a, pH1);
    // Layer 2
    node_ab_kernel<<<N_NODES / 16, 128>>>(pH1, W1b, b1b, pA, pB);
    aggregate_kernel<<<AGG_BLOCKS, 128, 65536>>>(pA, pB, W2b, b2b, pH2);
    // Dense tail
    tail_kernel<<<(N_NODES + 7) / 8, 256>>>(pH2, Wd1, bd1, Wd2, bd2, out);
}

// round 5
// speedup vs baseline: 2.5356x; 1.2829x over previous
#include <cuda_runtime.h>
#include <cuda_bf16.h>
#include <cstdint>

// Problem constants
#define N_NODES 50000
#define N_EDGES 800000
#define N_TILES (N_EDGES / 128)   // 6250 exact

// ---------------- scratch (device globals; no allocation allowed) ------------
__device__ int   g_cnt[N_NODES];
__device__ int   g_rowstart[N_NODES + 1];
__device__ int   g_wp[N_NODES];
__device__ int   g_srcs[N_EDGES];          // senders sorted by receiver
__device__ int   g_rcv[N_EDGES];           // receivers sorted (run ids)
__device__ float g_A[N_NODES * 64];        // x @ W1_top + b1
__device__ float g_B[N_NODES * 64];        // x @ W1_bot
__device__ float g_accum[N_NODES * 128];   // segment sums
__device__ float g_h1[N_NODES * 128];      // layer-1 output
__device__ float g_h2[N_NODES * 128];      // layer-2 output

// ---------------- helpers -----------------------------------------------------
__device__ __forceinline__ uint32_t f2tf32(float x) {
    uint32_t r;
    asm("cvt.rna.tf32.f32 %0, %1;" : "=r"(r) : "f"(x));
    return r;
}
__device__ __forceinline__ void mma_tf32(float* d, const uint32_t* a,
                                         uint32_t b0, uint32_t b1) {
    asm volatile(
        "mma.sync.aligned.m16n8k8.row.col.f32.tf32.tf32.f32 "
        "{%0,%1,%2,%3}, {%4,%5,%6,%7}, {%8,%9}, {%0,%1,%2,%3};"
        : "+f"(d[0]), "+f"(d[1]), "+f"(d[2]), "+f"(d[3])
        : "r"(a[0]), "r"(a[1]), "r"(a[2]), "r"(a[3]), "r"(b0), "r"(b1));
}

// ---------------- CSR construction ------------------------------------------
__global__ void zero_cnt_kernel() {
    int i = blockIdx.x * blockDim.x + threadIdx.x;
    if (i < N_NODES) g_cnt[i] = 0;
}

__global__ void hist_kernel(const int* __restrict__ receivers) {
    int e = blockIdx.x * blockDim.x + threadIdx.x;
    if (e < N_EDGES) atomicAdd(&g_cnt[receivers[e]], 1);
}

__global__ void scan_kernel() {
    __shared__ int wsum[32];
    __shared__ int carry;
    int t = threadIdx.x;
    int lane = t & 31, wid = t >> 5;
    if (t == 0) carry = 0;
    __syncthreads();
    for (int base = 0; base < N_NODES; base += 1024) {
        int i = base + t;
        int v = (i < N_NODES) ? g_cnt[i] : 0;
        int x = v;
#pragma unroll
        for (int o = 1; o < 32; o <<= 1) {
            int y = __shfl_up_sync(0xffffffffu, x, o);
            if (lane >= o) x += y;
        }
        if (lane == 31) wsum[wid] = x;
        __syncthreads();
        if (wid == 0) {
            int s = wsum[lane];
#pragma unroll
            for (int o = 1; o < 32; o <<= 1) {
                int y = __shfl_up_sync(0xffffffffu, s, o);
                if (lane >= o) s += y;
            }
            wsum[lane] = s;
        }
        __syncthreads();
        int excl = carry + (x - v) + (wid > 0 ? wsum[wid - 1] : 0);
        if (i < N_NODES) { g_rowstart[i] = excl; g_wp[i] = excl; }
        __syncthreads();
        if (t == 0) carry += wsum[31];
        __syncthreads();
    }
    if (t == 0) g_rowstart[N_NODES] = carry;
}

__global__ void fill_kernel(const int* __restrict__ senders,
                            const int* __restrict__ receivers) {
    int e = blockIdx.x * blockDim.x + threadIdx.x;
    if (e < N_EDGES) {
        int r = receivers[e];
        int pos = atomicAdd(&g_wp[r], 1);
        g_srcs[pos] = senders[e];
        g_rcv[pos] = r;
    }
}

// ---------------- per-node A/B precompute ------------------------------------
__global__ __launch_bounds__(128) void node_ab_kernel(
    const float* __restrict__ in, const float* __restrict__ W1,
    const float* __restrict__ b1, float* __restrict__ A, float* __restrict__ B) {
    __shared__ float xs[16][128];
    int t = threadIdx.x;
    int n0 = blockIdx.x * 16;
    {
        const float4* src = (const float4*)(in + (size_t)n0 * 128);
        float4* dst = (float4*)&xs[0][0];
#pragma unroll
        for (int i = 0; i < 4; i++) dst[t + i * 128] = src[t + i * 128];
    }
    __syncthreads();
    int half = t >> 6, j = t & 63;
    const float* Wb = W1 + half * (128 * 64) + j;
    float acc[16];
    float binit = half ? 0.f : b1[j];
#pragma unroll
    for (int nn = 0; nn < 16; nn++) acc[nn] = binit;
#pragma unroll 4
    for (int k = 0; k < 128; k++) {
        float w = __ldg(Wb + k * 64);
#pragma unroll
        for (int nn = 0; nn < 16; nn++) acc[nn] = fmaf(xs[nn][k], w, acc[nn]);
    }
    float* out = half ? B : A;
#pragma unroll
    for (int nn = 0; nn < 16; nn++) out[(size_t)(n0 + nn) * 64 + j] = acc[nn];
}

// ---------------- zero accum --------------------------------------------------
__global__ void zero_accum_kernel() {
    int i = blockIdx.x * blockDim.x + threadIdx.x;
    float4* p = (float4*)g_accum;
    if (i < N_NODES * 32) p[i] = make_float4(0.f, 0.f, 0.f, 0.f);
}

// ---------------- tensor-core edge kernel (mma.sync tf32) --------------------
// Tile = 128 edges (M=128), K=64, N=128. Block = 4 warps; warp w owns rows
// [32w,32w+32). A built in smem stride 68 (bank = lane, conflict-free frag
// loads). W2^T pre-packed fragment-ordered (LDS.64 conflict-free). 256 mma
// per warp per tile, D in 128 regs. Epilogue in two 64-col passes over a msg
// buffer aliasing the A tile; receiver-sorted segmented reduce (interior runs
// plain store, span-boundary runs atomicAdd).
#define SM_BFRAG 0        // 16*8*32*2 u32 = 32768 B
#define SM_A     32768    // 128*68*4 = 34816 B (aliased by msg 128*66*4)
#define SM_BIAS  67584    // 128 f = 512 B
#define SM_RS    68096    // 129 ints = 516 B
#define SM_TOTAL 68640

__global__ void __launch_bounds__(128, 2) edge_mma_kernel(
    const float* __restrict__ Apre, const float* __restrict__ Bpre,
    const float* __restrict__ W2, const float* __restrict__ b2) {
    extern __shared__ char smem[];
    uint32_t* Bfrag = (uint32_t*)(smem + SM_BFRAG);
    float* As   = (float*)(smem + SM_A);
    float* msg  = (float*)(smem + SM_A);
    float* bias = (float*)(smem + SM_BIAS);
    int*   rs   = (int*)(smem + SM_RS);
    int tid = threadIdx.x, w = tid >> 5, lane = tid & 31;

    // Pack W2^T into fragment order: pair idx = (nt*8 + k)*32 + t holds
    // {B(k-row = 8k + t%4, n = nt*8 + t/4), B(k-row + 4, n)}, B = W2^T.
    for (int idx = tid; idx < 16 * 8 * 32; idx += 128) {
        int nt = idx >> 8;
        int k  = (idx >> 5) & 7;
        int t  = idx & 31;
        int n  = nt * 8 + (t >> 2);
        int kc = k * 8 + (t & 3);
        Bfrag[idx * 2 + 0] = f2tf32(W2[kc * 128 + n]);
        Bfrag[idx * 2 + 1] = f2tf32(W2[(kc + 4) * 128 + n]);
    }
    bias[tid] = b2[tid];
    if (tid == 0) rs[128] = -1;
    __syncthreads();

    const float2* A2 = (const float2*)Apre;
    const float2* B2 = (const float2*)Bpre;
    const uint2*  Bf2 = (const uint2*)Bfrag;

    for (int tile = blockIdx.x; tile < N_TILES; tile += gridDim.x) {
        __syncthreads();   // prev tile's msg/rs fully consumed
        int e0 = tile * 128;
        // ---- build A rows (warp-private rows; no sync needed before MMA)
        int myE = e0 + w * 32 + lane;
        int s_l = g_srcs[myE];
        int r_l = g_rcv[myE];
        rs[w * 32 + lane] = r_l;
#pragma unroll 4
        for (int j = 0; j < 32; j++) {
            int s = __shfl_sync(0xffffffffu, s_l, j);
            int r = __shfl_sync(0xffffffffu, r_l, j);
            float2 va = A2[(size_t)r * 32 + lane];
            float2 vb = B2[(size_t)s * 32 + lane];
            uint32_t t0 = f2tf32(fmaxf(va.x + vb.x, 0.f));
            uint32_t t1 = f2tf32(fmaxf(va.y + vb.y, 0.f));
            *(uint2*)&As[(w * 32 + j) * 68 + 2 * lane] = make_uint2(t0, t1);
        }
        // ---- MMA: D[2 mtiles][16 ntiles][4]
        float d[2][16][4];
#pragma unroll
        for (int mt = 0; mt < 2; mt++)
#pragma unroll
            for (int nt = 0; nt < 16; nt++)
#pragma unroll
                for (int q = 0; q < 4; q++) d[mt][nt][q] = 0.f;
        const uint32_t* abase =
            (const uint32_t*)&As[(w * 32 + (lane >> 2)) * 68 + (lane & 3)];
        for (int k = 0; k < 8; k++) {
            uint32_t a[2][4];
#pragma unroll
            for (int mt = 0; mt < 2; mt++) {
                const uint32_t* ab = abase + mt * (16 * 68) + k * 8;
                a[mt][0] = ab[0];
                a[mt][1] = ab[8 * 68];
                a[mt][2] = ab[4];
                a[mt][3] = ab[8 * 68 + 4];
            }
            const uint2* bp = Bf2 + k * 32 + lane;
#pragma unroll
            for (int nt = 0; nt < 16; nt++) {
                uint2 bb = bp[nt * 256];
                mma_tf32(d[0][nt], a[0], bb.x, bb.y);
                mma_tf32(d[1][nt], a[1], bb.x, bb.y);
            }
        }
        __syncthreads();   // all warps done reading As before msg overwrites
        // ---- two epilogue+reduce passes (cols [0,64) then [64,128))
#pragma unroll
        for (int p = 0; p < 2; p++) {
#pragma unroll
            for (int mt = 0; mt < 2; mt++) {
                int row = w * 32 + mt * 16 + (lane >> 2);
#pragma unroll
                for (int ntl = 0; ntl < 8; ntl++) {
                    int nt = p * 8 + ntl;
                    int col = nt * 8 + 2 * (lane & 3);
                    int lcol = col - p * 64;
                    float2 bv = *(float2*)&bias[col];
                    float2 v0, v1;
                    v0.x = fmaxf(d[mt][nt][0] + bv.x, 0.f);
                    v0.y = fmaxf(d[mt][nt][1] + bv.y, 0.f);
                    v1.x = fmaxf(d[mt][nt][2] + bv.x, 0.f);
                    v1.y = fmaxf(d[mt][nt][3] + bv.y, 0.f);
                    *(float2*)&msg[row * 66 + lcol] = v0;
                    *(float2*)&msg[(row + 8) * 66 + lcol] = v1;
                }
            }
            __syncthreads();
            // segmented reduce: thread = (row-half, channel)
            {
                int h = tid >> 6, c = tid & 63;
                int elo = h * 64, ehi = elo + 64;
                float s = 0.f;
                int rstart = elo;
                int cur = rs[elo];
                for (int e = elo; e < ehi; e++) {
                    s += msg[e * 66 + c];
                    int nxt = rs[e + 1];           // rs[128] = -1 sentinel
                    bool last = (e == ehi - 1) || (nxt != cur);
                    if (last) {
                        float* dst = &g_accum[(size_t)cur * 128 + p * 64 + c];
                        if (rstart == elo || e == ehi - 1) atomicAdd(dst, s);
                        else *dst = s;
                        s = 0.f;
                        rstart = e + 1;
                        cur = nxt;
                    }
                }
            }
            if (p == 0) __syncthreads();   // before pass1 overwrites msg
        }
    }
}

// ---------------- finalize: mean ---------------------------------------------
__global__ void finalize_kernel(float* __restrict__ h) {
    int i = blockIdx.x * blockDim.x + threadIdx.x;
    if (i < N_NODES * 128) {
        int n = i >> 7;
        int c = g_cnt[n];
        h[i] = (c > 0) ? g_accum[i] / (float)c : 0.f;
    }
}

// ---------------- dense tail --------------------------------------------------
__global__ __launch_bounds__(256) void tail_kernel(
    const float* __restrict__ h, const float* __restrict__ Wd1,
    const float* __restrict__ bd1, const float* __restrict__ Wd2,
    const float* __restrict__ bd2, float* __restrict__ out) {
    __shared__ float Ws[128 * 64];
    int t = threadIdx.x;
    {
        const float4* src = (const float4*)Wd1;
        float4* dst = (float4*)Ws;
#pragma unroll
        for (int i = 0; i < 8; i++) dst[t + i * 256] = src[t + i * 256];
    }
    __syncthreads();
    int warp = t >> 5, lane = t & 31;
    int n = blockIdx.x * 8 + warp;
    if (n >= N_NODES) return;
    float x0 = h[(size_t)n * 128 + lane];
    float x1 = h[(size_t)n * 128 + 32 + lane];
    float x2 = h[(size_t)n * 128 + 64 + lane];
    float x3 = h[(size_t)n * 128 + 96 + lane];
    float g0 = bd1[lane], g1 = bd1[lane + 32];
#pragma unroll
    for (int kk = 0; kk < 32; kk++) {
        float xk;
        xk = __shfl_sync(0xffffffffu, x0, kk);
        g0 = fmaf(xk, Ws[kk * 64 + lane], g0);
        g1 = fmaf(xk, Ws[kk * 64 + lane + 32], g1);
        xk = __shfl_sync(0xffffffffu, x1, kk);
        g0 = fmaf(xk, Ws[(kk + 32) * 64 + lane], g0);
        g1 = fmaf(xk, Ws[(kk + 32) * 64 + lane + 32], g1);
        xk = __shfl_sync(0xffffffffu, x2, kk);
        g0 = fmaf(xk, Ws[(kk + 64) * 64 + lane], g0);
        g1 = fmaf(xk, Ws[(kk + 64) * 64 + lane + 32], g1);
        xk = __shfl_sync(0xffffffffu, x3, kk);
        g0 = fmaf(xk, Ws[(kk + 96) * 64 + lane], g0);
        g1 = fmaf(xk, Ws[(kk + 96) * 64 + lane + 32], g1);
    }
    g0 = fmaxf(g0, 0.f);
    g1 = fmaxf(g1, 0.f);
    float p = g0 * Wd2[lane] + g1 * Wd2[lane + 32];
#pragma unroll
    for (int o = 16; o > 0; o >>= 1) p += __shfl_xor_sync(0xffffffffu, p, o);
    if (lane == 0) out[n] = p + bd2[0];
}

// ---------------- launch ------------------------------------------------------
extern "C" void kernel_launch(void* const* d_in, const int* in_sizes, int n_in,
                              void* d_out, int out_size) {
    const float* x         = (const float*)d_in[0];
    const int*   senders   = (const int*)d_in[1];
    const int*   receivers = (const int*)d_in[2];
    const float* W1a = (const float*)d_in[3];
    const float* b1a = (const float*)d_in[4];
    const float* W2a = (const float*)d_in[5];
    const float* b2a = (const float*)d_in[6];
    const float* W1b = (const float*)d_in[7];
    const float* b1b = (const float*)d_in[8];
    const float* W2b = (const float*)d_in[9];
    const float* b2b = (const float*)d_in[10];
    const float* Wd1 = (const float*)d_in[11];
    const float* bd1 = (const float*)d_in[12];
    const float* Wd2 = (const float*)d_in[13];
    const float* bd2 = (const float*)d_in[14];
    float* out = (float*)d_out;

    static float* pA = nullptr;
    static float* pB = nullptr;
    static float* pH1 = nullptr;
    static float* pH2 = nullptr;
    if (!pA) {
        cudaGetSymbolAddress((void**)&pA, g_A);
        cudaGetSymbolAddress((void**)&pB, g_B);
        cudaGetSymbolAddress((void**)&pH1, g_h1);
        cudaGetSymbolAddress((void**)&pH2, g_h2);
        cudaFuncSetAttribute(edge_mma_kernel,
                             cudaFuncAttributeMaxDynamicSharedMemorySize, SM_TOTAL);
    }

    // CSR build
    zero_cnt_kernel<<<(N_NODES + 255) / 256, 256>>>();
    hist_kernel<<<(N_EDGES + 255) / 256, 256>>>(receivers);
    scan_kernel<<<1, 1024>>>();
    fill_kernel<<<(N_EDGES + 255) / 256, 256>>>(senders, receivers);

    const int MMA_BLOCKS = 296;   // 2 per SM

    // Layer 1
    node_ab_kernel<<<N_NODES / 16, 128>>>(x, W1a, b1a, pA, pB);
    zero_accum_kernel<<<(N_NODES * 32 + 255) / 256, 256>>>();
    edge_mma_kernel<<<MMA_BLOCKS, 128, SM_TOTAL>>>(pA, pB, W2a, b2a);
    finalize_kernel<<<(N_NODES * 128 + 255) / 256, 256>>>(pH1);
    // Layer 2
    node_ab_kernel<<<N_NODES / 16, 128>>>(pH1, W1b, b1b, pA, pB);
    zero_accum_kernel<<<(N_NODES * 32 + 255) / 256, 256>>>();
    edge_mma_kernel<<<MMA_BLOCKS, 128, SM_TOTAL>>>(pA, pB, W2b, b2b);
    finalize_kernel<<<(N_NODES * 128 + 255) / 256, 256>>>(pH2);
    // Dense tail
    tail_kernel<<<(N_NODES + 7) / 8, 256>>>(pH2, Wd1, bd1, Wd2, bd2, out);
}